// round 6
// baseline (speedup 1.0000x reference)
#include <cuda_runtime.h>
#include <math.h>

#define HW 65536
#define RATIO (127.0f / 255.0f)

// ---------------- scratch (device globals; no allocation) ----------------
__device__ __align__(16) float g_sage[4 * 3 * HW];  // enc planes: mx, av, c1(+b1)
__device__ __align__(16) float g_sagd[4 * 3 * HW];  // dec planes: mx, av, c1(+b1)
__device__ __align__(16) float g_spat[4 * HW];      // sigmoid spatial gate
__device__ float    g_encsum[4 * 128];
__device__ unsigned g_encmax[4 * 128];
__device__ float    g_decsum[4 * 256];
__device__ unsigned g_decmax[4 * 256];
__device__ __align__(16) float g_ch[4 * 128];       // sigmoid channel gate

// monotone float<->uint map for atomicMax on floats
__device__ __forceinline__ unsigned f2o(float f) {
    unsigned u = __float_as_uint(f);
    return (u & 0x80000000u) ? ~u : (u | 0x80000000u);
}
__device__ __forceinline__ float o2f(unsigned u) {
    return (u & 0x80000000u) ? __uint_as_float(u & 0x7fffffffu) : __uint_as_float(~u);
}

// ================= init =================
__global__ void k_init() {
    int t = blockIdx.x * blockDim.x + threadIdx.x;
    if (t < 512)  { g_encsum[t] = 0.f; g_encmax[t] = 0x007fffffu; }  // f2o(-inf)
    if (t < 1024) { g_decsum[t] = 0.f; g_decmax[t] = 0x80000000u; }  // f2o(0); relu => max>=0
}

// ================= fused encoder: per-pixel planes + per-channel stats =================
// grid (64, 4) x 256 threads: thread = column x, 4 rows y0..y0+3
__global__ void __launch_bounds__(256) k_enc(const float* __restrict__ xe,
                                             const float* __restrict__ sw1e,
                                             const float* __restrict__ sb1e) {
    __shared__ float sw[128];
    const int t = threadIdx.x;
    if (t < 128) sw[t] = sw1e[t];
    __syncthreads();
    const int y0 = blockIdx.x * 4, b = blockIdx.y;
    const float* base = xe + (size_t)b * 128 * HW + y0 * 256 + t;

    float pm[4], ps[4] = {0, 0, 0, 0}, pd[4] = {0, 0, 0, 0};
#pragma unroll
    for (int k = 0; k < 4; k++) pm[k] = -3.4e38f;

    for (int c = 0; c < 128; c++) {
        const float* p = base + (size_t)c * HW;
        float v0 = p[0], v1 = p[256], v2 = p[512], v3 = p[768];
        float wc = sw[c];
        pm[0] = fmaxf(pm[0], v0); ps[0] += v0; pd[0] = fmaf(wc, v0, pd[0]);
        pm[1] = fmaxf(pm[1], v1); ps[1] += v1; pd[1] = fmaf(wc, v1, pd[1]);
        pm[2] = fmaxf(pm[2], v2); ps[2] += v2; pd[2] = fmaf(wc, v2, pd[2]);
        pm[3] = fmaxf(pm[3], v3); ps[3] += v3; pd[3] = fmaf(wc, v3, pd[3]);
        float cs = (v0 + v1) + (v2 + v3);
        float cm = fmaxf(fmaxf(v0, v1), fmaxf(v2, v3));
#pragma unroll
        for (int o = 16; o; o >>= 1) {
            cs += __shfl_xor_sync(0xffffffffu, cs, o);
            cm = fmaxf(cm, __shfl_xor_sync(0xffffffffu, cm, o));
        }
        if ((t & 31) == 0) {
            atomicAdd(&g_encsum[b * 128 + c], cs);
            atomicMax(&g_encmax[b * 128 + c], f2o(cm));
        }
    }
    const float b1 = sb1e[0];
    const size_t eb = (size_t)b * 3 * HW;
#pragma unroll
    for (int k = 0; k < 4; k++) {
        int p = (y0 + k) * 256 + t;
        g_sage[eb + p]          = pm[k];
        g_sage[eb + HW + p]     = ps[k] * (1.f / 128.f);
        g_sage[eb + 2 * HW + p] = pd[k] + b1;
    }
}

// ================= fused decoder: bilinear+relu planes + per-channel stats =================
// grid (64, 4) x 256 threads: thread = column x, 4 rows y0..y0+3.
// Stages 4 clamped source rows (512 floats) per channel; 4 channels per barrier round,
// double-buffered: LDG next group early, compute current, STS, one sync per round.
__global__ void __launch_bounds__(256) k_dec(const float* __restrict__ xd,
                                             const float* __restrict__ sw1d,
                                             const float* __restrict__ sb1d) {
    __shared__ float sbuf[2][4 * 512];   // [buf][channel-in-group * 512 + row*128 + col]
    __shared__ float sw[256];
    const int t = threadIdx.x;
    sw[t] = sw1d[t];

    const int y0 = blockIdx.x * 4, b = blockIdx.y;
    // x-direction (reference-exact)
    float px = (float)t * RATIO;
    int j0 = min((int)floorf(px), 127), j1 = min(j0 + 1, 127);
    float wx = px - (float)j0;
    // y-direction: 4 rows, staged rows base..base+3 (clamped)
    const int base_row = (int)floorf((float)y0 * RATIO);
    float wy[4]; int lo[4];
#pragma unroll
    for (int k = 0; k < 4; k++) {
        float py = (float)(y0 + k) * RATIO;
        int i0 = min((int)floorf(py), 127);
        wy[k] = py - (float)i0;
        lo[k] = i0 - base_row;           // 0..2 (uniform across block)
    }
    // staging offsets: elem e = t (rows 0-1), e = t+256 (rows 2-3)
    const int r0 = min(base_row + (t >> 7), 127);
    const int r1 = min(base_row + 2 + (t >> 7), 127);
    const int g0 = r0 * 128 + (t & 127);
    const int g1 = r1 * 128 + (t & 127);
    const float* pcb = xd + (size_t)b * 256 * 16384;

    // prologue: stage group 0
    {
        float a0 = pcb[0 * 16384 + g0], a1 = pcb[0 * 16384 + g1];
        float b0 = pcb[1 * 16384 + g0], b1v = pcb[1 * 16384 + g1];
        float c0 = pcb[2 * 16384 + g0], c1 = pcb[2 * 16384 + g1];
        float d0 = pcb[3 * 16384 + g0], d1 = pcb[3 * 16384 + g1];
        sbuf[0][0 * 512 + t] = a0; sbuf[0][0 * 512 + 256 + t] = a1;
        sbuf[0][1 * 512 + t] = b0; sbuf[0][1 * 512 + 256 + t] = b1v;
        sbuf[0][2 * 512 + t] = c0; sbuf[0][2 * 512 + 256 + t] = c1;
        sbuf[0][3 * 512 + t] = d0; sbuf[0][3 * 512 + 256 + t] = d1;
    }
    __syncthreads();

    float pmx[4] = {0, 0, 0, 0}, psm[4] = {0, 0, 0, 0}, pdt[4] = {0, 0, 0, 0};

    for (int g = 0; g < 64; g++) {
        const int cur = g & 1, nxt = cur ^ 1;
        float rr[8];
        const bool pf = (g + 1 < 64);
        if (pf) {
            const float* pn = pcb + (size_t)(g + 1) * 4 * 16384;
#pragma unroll
            for (int q = 0; q < 4; q++) {
                rr[q * 2]     = pn[(size_t)q * 16384 + g0];
                rr[q * 2 + 1] = pn[(size_t)q * 16384 + g1];
            }
        }
#pragma unroll
        for (int q = 0; q < 4; q++) {
            const int c = g * 4 + q;
            const float* S = &sbuf[cur][q * 512];
            float h0, h1, h2, h3;
            { float a = S[j0],       bb = S[j1];       h0 = fmaf(wx, bb - a, a); }
            { float a = S[128 + j0], bb = S[128 + j1]; h1 = fmaf(wx, bb - a, a); }
            { float a = S[256 + j0], bb = S[256 + j1]; h2 = fmaf(wx, bb - a, a); }
            { float a = S[384 + j0], bb = S[384 + j1]; h3 = fmaf(wx, bb - a, a); }
            const float wc = sw[c];
            float cs = 0.f, cm = 0.f;
#pragma unroll
            for (int k = 0; k < 4; k++) {
                float hl = (lo[k] == 0) ? h0 : ((lo[k] == 1) ? h1 : h2);
                float hh = (lo[k] == 0) ? h1 : ((lo[k] == 1) ? h2 : h3);
                float v = fmaf(wy[k], hh - hl, hl);
                v = fmaxf(v, 0.f);
                pmx[k] = fmaxf(pmx[k], v);
                psm[k] += v;
                pdt[k] = fmaf(wc, v, pdt[k]);
                cs += v;
                cm = fmaxf(cm, v);
            }
#pragma unroll
            for (int o = 16; o; o >>= 1) {
                cs += __shfl_xor_sync(0xffffffffu, cs, o);
                cm = fmaxf(cm, __shfl_xor_sync(0xffffffffu, cm, o));
            }
            if ((t & 31) == 0) {
                atomicAdd(&g_decsum[b * 256 + c], cs);
                atomicMax(&g_decmax[b * 256 + c], f2o(cm));
            }
        }
        if (pf) {
#pragma unroll
            for (int q = 0; q < 4; q++) {
                sbuf[nxt][q * 512 + t]       = rr[q * 2];
                sbuf[nxt][q * 512 + 256 + t] = rr[q * 2 + 1];
            }
        }
        __syncthreads();
    }

    const float b1 = sb1d[0];
    const size_t db = (size_t)b * 3 * HW;
#pragma unroll
    for (int k = 0; k < 4; k++) {
        int p = (y0 + k) * 256 + t;
        g_sagd[db + p]          = pmx[k];
        g_sagd[db + HW + p]     = psm[k] * (1.f / 256.f);
        g_sagd[db + 2 * HW + p] = pdt[k] + b1;
    }
}

// ================= channel MLP =================
__global__ void k_mlp(const float* __restrict__ cwea, const float* __restrict__ cbea,
                      const float* __restrict__ cwem, const float* __restrict__ cbem,
                      const float* __restrict__ cwda, const float* __restrict__ cbda,
                      const float* __restrict__ cwdm, const float* __restrict__ cbdm,
                      const float* __restrict__ cwf,  const float* __restrict__ cbf) {
    __shared__ float tsm[64];
    const int t = threadIdx.x;   // 512 threads
    if (t < 64) {
        int b = t >> 4, n = t & 15;
        float acc = cbea[n] + cbem[n] + cbda[n] + cbdm[n];
        for (int c = 0; c < 128; c++) {
            float mean = g_encsum[b * 128 + c] * (1.f / 65536.f);
            float mx   = o2f(g_encmax[b * 128 + c]);
            acc += mean * cwea[n * 128 + c] + mx * cwem[n * 128 + c];
        }
        for (int c = 0; c < 256; c++) {
            float mean = g_decsum[b * 256 + c] * (1.f / 65536.f);
            float mx   = o2f(g_decmax[b * 256 + c]);
            acc += mean * cwda[n * 256 + c] + mx * cwdm[n * 256 + c];
        }
        tsm[t] = acc;
    }
    __syncthreads();
    int b = t >> 7, o = t & 127;
    float a = cbf[o];
#pragma unroll
    for (int n = 0; n < 16; n++) a = fmaf(tsm[b * 16 + n], cwf[o * 16 + n], a);
    g_ch[t] = 1.f / (1.f + __expf(-a));
}

// ================= fused 7x7 conv (6 planes) + sigmoid =================
// grid (16, 16, 4): 16x16 output tile, 256 threads, 1 output/thread
__global__ void __launch_bounds__(256) k_conv(const float* __restrict__ sw2e,
                                              const float* __restrict__ sw2d,
                                              const float* __restrict__ sb2e,
                                              const float* __restrict__ sb2d) {
    __shared__ float pl[6][22 * 22];
    __shared__ float wsm[294];
    __shared__ float bv;
    const int tid = threadIdx.x;
    const int X0 = blockIdx.x * 16, Y0 = blockIdx.y * 16, b = blockIdx.z;
    for (int i = tid; i < 294; i += 256)
        wsm[i] = (i < 147) ? sw2e[i] : sw2d[i - 147];
    if (tid == 0) bv = sb2e[0] + sb2d[0];
    const size_t eb = (size_t)b * 3 * HW;
    for (int idx = tid; idx < 22 * 22; idx += 256) {
        int ry = idx / 22, rx = idx - ry * 22;
        int gy = Y0 + ry - 3, gx = X0 + rx - 3;
        float v0 = 0, v1 = 0, v2 = 0, v3 = 0, v4 = 0, v5 = 0;
        if (gy >= 0 && gy < 256 && gx >= 0 && gx < 256) {
            int p = gy * 256 + gx;
            v0 = g_sage[eb + p];
            v1 = g_sage[eb + HW + p];
            v2 = g_sage[eb + 2 * HW + p];
            v3 = g_sagd[eb + p];
            v4 = g_sagd[eb + HW + p];
            v5 = g_sagd[eb + 2 * HW + p];
        }
        pl[0][idx] = v0; pl[1][idx] = v1; pl[2][idx] = v2;
        pl[3][idx] = v3; pl[4][idx] = v4; pl[5][idx] = v5;
    }
    __syncthreads();
    const int tx = tid & 15, ty = tid >> 4;
    float acc = bv;
    for (int pp = 0; pp < 6; pp++)
#pragma unroll
        for (int ky = 0; ky < 7; ky++)
#pragma unroll
            for (int kx = 0; kx < 7; kx++)
                acc = fmaf(pl[pp][(ty + ky) * 22 + tx + kx], wsm[pp * 49 + ky * 7 + kx], acc);
    g_spat[(size_t)b * HW + (Y0 + ty) * 256 + X0 + tx] = 1.f / (1.f + __expf(-acc));
}

// ================= final multiply =================
// grid (64, 512): blockIdx.y = b*128+c, float4 per thread
__global__ void __launch_bounds__(256) k_final(const float* __restrict__ xe,
                                               float* __restrict__ out) {
    const int bc = blockIdx.y;
    const int b  = bc >> 7;
    const int i  = blockIdx.x * 256 + threadIdx.x;
    const float s = g_ch[bc];
    float4 xv = reinterpret_cast<const float4*>(xe)[(size_t)bc * 16384 + i];
    float4 sp = reinterpret_cast<const float4*>(g_spat)[(size_t)b * 16384 + i];
    float4 o;
    o.x = xv.x * sp.x * s;
    o.y = xv.y * sp.y * s;
    o.z = xv.z * sp.z * s;
    o.w = xv.w * sp.w * s;
    reinterpret_cast<float4*>(out)[(size_t)bc * 16384 + i] = o;
}

// ================= launch =================
extern "C" void kernel_launch(void* const* d_in, const int* in_sizes, int n_in,
                              void* d_out, int out_size) {
    const float* xe   = (const float*)d_in[0];
    const float* xd   = (const float*)d_in[1];
    const float* cwea = (const float*)d_in[2];
    const float* cbea = (const float*)d_in[3];
    const float* cwem = (const float*)d_in[4];
    const float* cbem = (const float*)d_in[5];
    const float* cwda = (const float*)d_in[6];
    const float* cbda = (const float*)d_in[7];
    const float* cwdm = (const float*)d_in[8];
    const float* cbdm = (const float*)d_in[9];
    const float* cwf  = (const float*)d_in[10];
    const float* cbf  = (const float*)d_in[11];
    const float* sw1e = (const float*)d_in[12];
    const float* sb1e = (const float*)d_in[13];
    const float* sw2e = (const float*)d_in[14];
    const float* sb2e = (const float*)d_in[15];
    const float* sw1d = (const float*)d_in[16];
    const float* sb1d = (const float*)d_in[17];
    const float* sw2d = (const float*)d_in[18];
    const float* sb2d = (const float*)d_in[19];
    float* out = (float*)d_out;

    k_init<<<1, 1024>>>();
    k_enc<<<dim3(64, 4), 256>>>(xe, sw1e, sb1e);
    k_dec<<<dim3(64, 4), 256>>>(xd, sw1d, sb1d);
    k_mlp<<<1, 512>>>(cwea, cbea, cwem, cbem, cwda, cbda, cwdm, cbdm, cwf, cbf);
    k_conv<<<dim3(16, 16, 4), 256>>>(sw2e, sw2d, sb2e, sb2d);
    k_final<<<dim3(64, 512), 256>>>(xe, out);
}

// round 7
// speedup vs baseline: 1.7591x; 1.7591x over previous
#include <cuda_runtime.h>
#include <math.h>

#define HW 65536
#define RATIO (127.0f / 255.0f)

// ---------------- scratch (device globals; no allocation) ----------------
__device__ __align__(16) float g_sage[4 * 3 * HW];  // enc planes: mx, av, c1(+b1)
__device__ __align__(16) float g_sagd[4 * 3 * HW];  // dec planes: mx, av, c1(+b1)
__device__ __align__(16) float g_spat[4 * HW];      // sigmoid spatial gate
__device__ float g_encmean[4 * 128];
__device__ float g_encmax [4 * 128];
__device__ float g_decmean[4 * 256];
__device__ float g_decmax [4 * 256];
__device__ __align__(16) float g_ch[4 * 128];       // sigmoid channel gate

// ================= encoder per-pixel planes (float4) =================
// grid (128, 4) x 128 threads: block = rows 2*bx..2*bx+1; thread = (row, float4-col)
__global__ void __launch_bounds__(128) k_enc_pix(const float* __restrict__ xe,
                                                 const float* __restrict__ sw1e,
                                                 const float* __restrict__ sb1e) {
    __shared__ float sw[128];
    const int t = threadIdx.x;
    if (t < 128) sw[t] = sw1e[t];
    __syncthreads();
    const int y = blockIdx.x * 2 + (t >> 6), c4 = t & 63, b = blockIdx.y;
    const float4* base = (const float4*)(xe + (size_t)b * 128 * HW + y * 256) + c4;

    float4 mx = make_float4(-3.4e38f, -3.4e38f, -3.4e38f, -3.4e38f);
    float4 sm = make_float4(0.f, 0.f, 0.f, 0.f);
    float4 dt = make_float4(0.f, 0.f, 0.f, 0.f);
    for (int c = 0; c < 128; c++) {
        float4 v = base[(size_t)c * (HW / 4)];
        float wc = sw[c];
        mx.x = fmaxf(mx.x, v.x); sm.x += v.x; dt.x = fmaf(wc, v.x, dt.x);
        mx.y = fmaxf(mx.y, v.y); sm.y += v.y; dt.y = fmaf(wc, v.y, dt.y);
        mx.z = fmaxf(mx.z, v.z); sm.z += v.z; dt.z = fmaf(wc, v.z, dt.z);
        mx.w = fmaxf(mx.w, v.w); sm.w += v.w; dt.w = fmaf(wc, v.w, dt.w);
    }
    const float b1 = sb1e[0];
    sm.x *= (1.f / 128.f); sm.y *= (1.f / 128.f); sm.z *= (1.f / 128.f); sm.w *= (1.f / 128.f);
    dt.x += b1; dt.y += b1; dt.z += b1; dt.w += b1;
    const size_t p4 = (size_t)(y * 256) / 4 + c4;
    float4* eb = (float4*)(g_sage + (size_t)b * 3 * HW);
    eb[p4]              = mx;
    eb[HW / 4 + p4]     = sm;
    eb[2 * HW / 4 + p4] = dt;
}

// ================= encoder per-channel stats (float4, tree) =================
// grid (128, 4): c = blockIdx.x, b = blockIdx.y, 256 threads
__global__ void __launch_bounds__(256) k_enc_red(const float* __restrict__ xe) {
    __shared__ float ssum[256], smax[256];
    const int c = blockIdx.x, b = blockIdx.y, t = threadIdx.x;
    const float4* p = (const float4*)(xe + ((size_t)b * 128 + c) * HW);
    float s = 0.f, m = -3.4e38f;
    for (int i = t; i < HW / 4; i += 256) {
        float4 v = p[i];
        s += (v.x + v.y) + (v.z + v.w);
        m = fmaxf(m, fmaxf(fmaxf(v.x, v.y), fmaxf(v.z, v.w)));
    }
    ssum[t] = s; smax[t] = m;
    __syncthreads();
    for (int o = 128; o > 0; o >>= 1) {
        if (t < o) {
            ssum[t] += ssum[t + o];
            smax[t] = fmaxf(smax[t], smax[t + o]);
        }
        __syncthreads();
    }
    if (t == 0) {
        g_encmean[b * 128 + c] = ssum[0] * (1.f / 65536.f);
        g_encmax [b * 128 + c] = smax[0];
    }
}

// ================= decoder per-pixel planes (8 channels per barrier round) =================
// grid (256, 4) x 256 threads: block = output row y; thread = column
__global__ void __launch_bounds__(256) k_dec_pix(const float* __restrict__ xd,
                                                 const float* __restrict__ sw1d,
                                                 const float* __restrict__ sb1d) {
    __shared__ float sw[256];
    __shared__ float buf[2][8 * 256];  // [buf][q*256 + (0:128 row i0 | 128:256 row i1)]
    const int t = threadIdx.x, y = blockIdx.x, b = blockIdx.y;
    sw[t] = sw1d[t];

    float py = (float)y * RATIO;
    int i0 = min((int)floorf(py), 127), i1 = min(i0 + 1, 127);
    float wy = py - (float)i0;
    float px = (float)t * RATIO;
    int j0 = min((int)floorf(px), 127), j1 = min(j0 + 1, 127);
    float wx = px - (float)j0;

    const int goff = ((t >> 7) ? i1 : i0) * 128 + (t & 127);
    const float* pcb = xd + (size_t)b * 256 * 16384;

    // prologue: batch 0
#pragma unroll
    for (int q = 0; q < 8; q++)
        buf[0][q * 256 + t] = pcb[(size_t)q * 16384 + goff];
    __syncthreads();

    float mx = 0.f, sm = 0.f, dt = 0.f;
    for (int g = 0; g < 32; g++) {
        const int cur = g & 1;
        float rr[8];
        const bool pf = (g < 31);
        if (pf) {
            const float* pn = pcb + (size_t)(g + 1) * 8 * 16384;
#pragma unroll
            for (int q = 0; q < 8; q++) rr[q] = pn[(size_t)q * 16384 + goff];
        }
#pragma unroll
        for (int q = 0; q < 8; q++) {
            const int c = g * 8 + q;
            const float* S = &buf[cur][q * 256];
            float top = S[j0]       * (1.f - wx) + S[j1]       * wx;
            float bot = S[128 + j0] * (1.f - wx) + S[128 + j1] * wx;
            float v = top * (1.f - wy) + bot * wy;
            v = fmaxf(v, 0.f);
            mx = fmaxf(mx, v);
            sm += v;
            dt = fmaf(sw[c], v, dt);
        }
        if (pf) {
#pragma unroll
            for (int q = 0; q < 8; q++) buf[cur ^ 1][q * 256 + t] = rr[q];
        }
        __syncthreads();
    }
    const int p = y * 256 + t;
    const size_t db = (size_t)b * 3 * HW;
    g_sagd[db + p]          = mx;
    g_sagd[db + HW + p]     = sm * (1.f / 256.f);
    g_sagd[db + 2 * HW + p] = dt + sb1d[0];
}

// ================= decoder per-channel stats (18-row chunks, tree) =================
// grid (256, 4): c = blockIdx.x, b = blockIdx.y, 256 threads (thread = output column)
__global__ void __launch_bounds__(256) k_dec_red(const float* __restrict__ xd) {
    __shared__ float S[18 * 128];
    __shared__ float ssum[256], smax[256];
    const int c = blockIdx.x, b = blockIdx.y, t = threadIdx.x;
    const float* pc = xd + ((size_t)b * 256 + c) * 16384;
    float px = (float)t * RATIO;
    int j0 = min((int)floorf(px), 127), j1 = min(j0 + 1, 127);
    float wx = px - (float)j0;

    float s = 0.f, m = 0.f;
    for (int k = 0; k < 8; k++) {
        const int y0 = k * 32;
        const int base = (int)floorf((float)y0 * RATIO);
        __syncthreads();
        for (int e = t; e < 18 * 128; e += 256) {
            int r = e >> 7, col = e & 127;
            S[e] = pc[min(base + r, 127) * 128 + col];
        }
        __syncthreads();
#pragma unroll 4
        for (int j = 0; j < 32; j++) {
            int y = y0 + j;
            float py = (float)y * RATIO;
            int i0 = min((int)floorf(py), 127);
            float wy = py - (float)i0;
            int ri0 = i0 - base;
            int ri1 = min(i0 + 1, 127) - base;
            float top = S[ri0 * 128 + j0] * (1.f - wx) + S[ri0 * 128 + j1] * wx;
            float bot = S[ri1 * 128 + j0] * (1.f - wx) + S[ri1 * 128 + j1] * wx;
            float v = top * (1.f - wy) + bot * wy;
            v = fmaxf(v, 0.f);
            s += v;
            m = fmaxf(m, v);
        }
    }
    __syncthreads();
    ssum[t] = s; smax[t] = m;
    __syncthreads();
    for (int o = 128; o > 0; o >>= 1) {
        if (t < o) {
            ssum[t] += ssum[t + o];
            smax[t] = fmaxf(smax[t], smax[t + o]);
        }
        __syncthreads();
    }
    if (t == 0) {
        g_decmean[b * 256 + c] = ssum[0] * (1.f / 65536.f);
        g_decmax [b * 256 + c] = smax[0];
    }
}

// ================= channel MLP (parallel) =================
// grid (4): b = blockIdx.x, 256 threads: thread = (n 0..15, chunk 0..15)
__global__ void __launch_bounds__(256) k_mlp(
        const float* __restrict__ cwea, const float* __restrict__ cbea,
        const float* __restrict__ cwem, const float* __restrict__ cbem,
        const float* __restrict__ cwda, const float* __restrict__ cbda,
        const float* __restrict__ cwdm, const float* __restrict__ cbdm,
        const float* __restrict__ cwf,  const float* __restrict__ cbf) {
    __shared__ float part[256];
    __shared__ float tsm[16];
    const int b = blockIdx.x, t = threadIdx.x;
    const int n = t >> 4, ck = t & 15;
    float acc = 0.f;
#pragma unroll
    for (int i = 0; i < 8; i++) {          // enc channels: 8 per chunk
        int c = ck * 8 + i;
        acc += g_encmean[b * 128 + c] * cwea[n * 128 + c]
             + g_encmax [b * 128 + c] * cwem[n * 128 + c];
    }
#pragma unroll
    for (int i = 0; i < 16; i++) {         // dec channels: 16 per chunk
        int c = ck * 16 + i;
        acc += g_decmean[b * 256 + c] * cwda[n * 256 + c]
             + g_decmax [b * 256 + c] * cwdm[n * 256 + c];
    }
    if (ck == 0) acc += cbea[n] + cbem[n] + cbda[n] + cbdm[n];
    part[t] = acc;
    __syncthreads();
    for (int o = 8; o > 0; o >>= 1) {
        if (ck < o) part[t] += part[t + o];
        __syncthreads();
    }
    if (ck == 0) tsm[n] = part[t];
    __syncthreads();
    if (t < 128) {
        float a = cbf[t];
#pragma unroll
        for (int q = 0; q < 16; q++) a = fmaf(tsm[q], cwf[t * 16 + q], a);
        g_ch[b * 128 + t] = 1.f / (1.f + __expf(-a));
    }
}

// ================= fused 7x7 conv (6 planes) + sigmoid =================
// grid (16, 16, 4): 16x16 output tile, 256 threads, 1 output/thread
__global__ void __launch_bounds__(256) k_conv(const float* __restrict__ sw2e,
                                              const float* __restrict__ sw2d,
                                              const float* __restrict__ sb2e,
                                              const float* __restrict__ sb2d) {
    __shared__ float pl[6][22 * 22];
    __shared__ float wsm[294];
    __shared__ float bv;
    const int tid = threadIdx.x;
    const int X0 = blockIdx.x * 16, Y0 = blockIdx.y * 16, b = blockIdx.z;
    for (int i = tid; i < 294; i += 256)
        wsm[i] = (i < 147) ? sw2e[i] : sw2d[i - 147];
    if (tid == 0) bv = sb2e[0] + sb2d[0];
    const size_t eb = (size_t)b * 3 * HW;
    for (int idx = tid; idx < 22 * 22; idx += 256) {
        int ry = idx / 22, rx = idx - ry * 22;
        int gy = Y0 + ry - 3, gx = X0 + rx - 3;
        float v0 = 0, v1 = 0, v2 = 0, v3 = 0, v4 = 0, v5 = 0;
        if (gy >= 0 && gy < 256 && gx >= 0 && gx < 256) {
            int p = gy * 256 + gx;
            v0 = g_sage[eb + p];
            v1 = g_sage[eb + HW + p];
            v2 = g_sage[eb + 2 * HW + p];
            v3 = g_sagd[eb + p];
            v4 = g_sagd[eb + HW + p];
            v5 = g_sagd[eb + 2 * HW + p];
        }
        pl[0][idx] = v0; pl[1][idx] = v1; pl[2][idx] = v2;
        pl[3][idx] = v3; pl[4][idx] = v4; pl[5][idx] = v5;
    }
    __syncthreads();
    const int tx = tid & 15, ty = tid >> 4;
    float acc = bv;
    for (int pp = 0; pp < 6; pp++)
#pragma unroll
        for (int ky = 0; ky < 7; ky++)
#pragma unroll
            for (int kx = 0; kx < 7; kx++)
                acc = fmaf(pl[pp][(ty + ky) * 22 + tx + kx], wsm[pp * 49 + ky * 7 + kx], acc);
    g_spat[(size_t)b * HW + (Y0 + ty) * 256 + X0 + tx] = 1.f / (1.f + __expf(-acc));
}

// ================= final multiply =================
// grid (64, 512): blockIdx.y = b*128+c, float4 per thread
__global__ void __launch_bounds__(256) k_final(const float* __restrict__ xe,
                                               float* __restrict__ out) {
    const int bc = blockIdx.y;
    const int b  = bc >> 7;
    const int i  = blockIdx.x * 256 + threadIdx.x;
    const float s = g_ch[bc];
    float4 xv = reinterpret_cast<const float4*>(xe)[(size_t)bc * 16384 + i];
    float4 sp = reinterpret_cast<const float4*>(g_spat)[(size_t)b * 16384 + i];
    float4 o;
    o.x = xv.x * sp.x * s;
    o.y = xv.y * sp.y * s;
    o.z = xv.z * sp.z * s;
    o.w = xv.w * sp.w * s;
    reinterpret_cast<float4*>(out)[(size_t)bc * 16384 + i] = o;
}

// ================= launch =================
extern "C" void kernel_launch(void* const* d_in, const int* in_sizes, int n_in,
                              void* d_out, int out_size) {
    const float* xe   = (const float*)d_in[0];
    const float* xd   = (const float*)d_in[1];
    const float* cwea = (const float*)d_in[2];
    const float* cbea = (const float*)d_in[3];
    const float* cwem = (const float*)d_in[4];
    const float* cbem = (const float*)d_in[5];
    const float* cwda = (const float*)d_in[6];
    const float* cbda = (const float*)d_in[7];
    const float* cwdm = (const float*)d_in[8];
    const float* cbdm = (const float*)d_in[9];
    const float* cwf  = (const float*)d_in[10];
    const float* cbf  = (const float*)d_in[11];
    const float* sw1e = (const float*)d_in[12];
    const float* sb1e = (const float*)d_in[13];
    const float* sw2e = (const float*)d_in[14];
    const float* sb2e = (const float*)d_in[15];
    const float* sw1d = (const float*)d_in[16];
    const float* sb1d = (const float*)d_in[17];
    const float* sw2d = (const float*)d_in[18];
    const float* sb2d = (const float*)d_in[19];
    float* out = (float*)d_out;

    k_enc_pix<<<dim3(128, 4), 128>>>(xe, sw1e, sb1e);
    k_enc_red<<<dim3(128, 4), 256>>>(xe);
    k_dec_pix<<<dim3(256, 4), 256>>>(xd, sw1d, sb1d);
    k_dec_red<<<dim3(256, 4), 256>>>(xd);
    k_mlp<<<4, 256>>>(cwea, cbea, cwem, cbem, cwda, cbda, cwdm, cbdm, cwf, cbf);
    k_conv<<<dim3(16, 16, 4), 256>>>(sw2e, sw2d, sb2e, sb2d);
    k_final<<<dim3(64, 512), 256>>>(xe, out);
}

// round 8
// speedup vs baseline: 2.2791x; 1.2956x over previous
#include <cuda_runtime.h>
#include <math.h>

#define HW 65536
#define RATIO (127.0f / 255.0f)

// ---------------- scratch (device globals; no allocation) ----------------
__device__ __align__(16) float g_sage[4 * 3 * HW];  // enc planes: mx, av, c1(+b1)
__device__ __align__(16) float g_sagd[4 * 3 * HW];  // dec planes: mx, av, c1(+b1)
__device__ __align__(16) float g_spat[4 * HW];      // sigmoid spatial gate
__device__ float    g_encsum[4 * 128];
__device__ unsigned g_encmax[4 * 128];
__device__ float    g_decmean[4 * 256];
__device__ float    g_decmax [4 * 256];
__device__ __align__(16) float g_ch[4 * 128];       // sigmoid channel gate

// monotone float<->uint map for atomicMax on floats
__device__ __forceinline__ unsigned f2o(float f) {
    unsigned u = __float_as_uint(f);
    return (u & 0x80000000u) ? ~u : (u | 0x80000000u);
}
__device__ __forceinline__ float o2f(unsigned u) {
    return (u & 0x80000000u) ? __uint_as_float(u & 0x7fffffffu) : __uint_as_float(~u);
}

// ================= init (enc atomic targets only) =================
__global__ void k_init() {
    int t = threadIdx.x;
    if (t < 512) { g_encsum[t] = 0.f; g_encmax[t] = 0x007fffffu; }  // f2o(-inf)
}

// ================= fused encoder: planes + channel stats =================
// grid (128, 4) x 128 threads: block = 2 rows; thread = (row, float4-col)
__global__ void __launch_bounds__(128) k_enc(const float* __restrict__ xe,
                                             const float* __restrict__ sw1e,
                                             const float* __restrict__ sb1e) {
    __shared__ float sw[128];
    __shared__ float psum[4][128], pmax[4][128];
    const int t = threadIdx.x;
    if (t < 128) sw[t] = sw1e[t];
    __syncthreads();
    const int y = blockIdx.x * 2 + (t >> 6), c4 = t & 63, b = blockIdx.y;
    const int warp = t >> 5, lane = t & 31;
    const float4* base = (const float4*)(xe + (size_t)b * 128 * HW + y * 256) + c4;

    float4 mx = make_float4(-3.4e38f, -3.4e38f, -3.4e38f, -3.4e38f);
    float4 sm = make_float4(0.f, 0.f, 0.f, 0.f);
    float4 dt = make_float4(0.f, 0.f, 0.f, 0.f);
    float racc[4] = {0.f, 0.f, 0.f, 0.f};
    float rmx[4]  = {-3.4e38f, -3.4e38f, -3.4e38f, -3.4e38f};

#pragma unroll
    for (int q = 0; q < 4; q++) {          // channel slot (compile-time)
#pragma unroll 4
        for (int cc = 0; cc < 32; cc++) {  // channel within slot
            const int c = q * 32 + cc;
            float4 v = base[(size_t)c * (HW / 4)];
            float wc = sw[c];
            mx.x = fmaxf(mx.x, v.x); sm.x += v.x; dt.x = fmaf(wc, v.x, dt.x);
            mx.y = fmaxf(mx.y, v.y); sm.y += v.y; dt.y = fmaf(wc, v.y, dt.y);
            mx.z = fmaxf(mx.z, v.z); sm.z += v.z; dt.z = fmaf(wc, v.z, dt.z);
            mx.w = fmaxf(mx.w, v.w); sm.w += v.w; dt.w = fmaf(wc, v.w, dt.w);
            float cs = (v.x + v.y) + (v.z + v.w);
            float cm = fmaxf(fmaxf(v.x, v.y), fmaxf(v.z, v.w));
#pragma unroll
            for (int o = 16; o; o >>= 1) {
                cs += __shfl_xor_sync(0xffffffffu, cs, o);
                cm = fmaxf(cm, __shfl_xor_sync(0xffffffffu, cm, o));
            }
            if (lane == cc) { racc[q] += cs; rmx[q] = fmaxf(rmx[q], cm); }
        }
    }
#pragma unroll
    for (int q = 0; q < 4; q++) {
        psum[warp][q * 32 + lane] = racc[q];
        pmax[warp][q * 32 + lane] = rmx[q];
    }
    __syncthreads();
    if (t < 128) {
        float s = (psum[0][t] + psum[1][t]) + (psum[2][t] + psum[3][t]);
        float m = fmaxf(fmaxf(pmax[0][t], pmax[1][t]), fmaxf(pmax[2][t], pmax[3][t]));
        atomicAdd(&g_encsum[b * 128 + t], s);
        atomicMax(&g_encmax[b * 128 + t], f2o(m));
    }
    const float b1 = sb1e[0];
    sm.x *= (1.f / 128.f); sm.y *= (1.f / 128.f); sm.z *= (1.f / 128.f); sm.w *= (1.f / 128.f);
    dt.x += b1; dt.y += b1; dt.z += b1; dt.w += b1;
    const size_t p4 = (size_t)(y * 256) / 4 + c4;
    float4* eb = (float4*)(g_sage + (size_t)b * 3 * HW);
    eb[p4]              = mx;
    eb[HW / 4 + p4]     = sm;
    eb[2 * HW / 4 + p4] = dt;
}

// ================= decoder per-pixel planes (8 channels per barrier round) =================
// grid (256, 4) x 256 threads: block = output row y; thread = column
__global__ void __launch_bounds__(256) k_dec_pix(const float* __restrict__ xd,
                                                 const float* __restrict__ sw1d,
                                                 const float* __restrict__ sb1d) {
    __shared__ float sw[256];
    __shared__ float buf[2][8 * 256];
    const int t = threadIdx.x, y = blockIdx.x, b = blockIdx.y;
    sw[t] = sw1d[t];

    float py = (float)y * RATIO;
    int i0 = min((int)floorf(py), 127), i1 = min(i0 + 1, 127);
    float wy = py - (float)i0;
    float px = (float)t * RATIO;
    int j0 = min((int)floorf(px), 127), j1 = min(j0 + 1, 127);
    float wx = px - (float)j0;

    const int goff = ((t >> 7) ? i1 : i0) * 128 + (t & 127);
    const float* pcb = xd + (size_t)b * 256 * 16384;

#pragma unroll
    for (int q = 0; q < 8; q++)
        buf[0][q * 256 + t] = pcb[(size_t)q * 16384 + goff];
    __syncthreads();

    float mx = 0.f, sm = 0.f, dt = 0.f;
    for (int g = 0; g < 32; g++) {
        const int cur = g & 1;
        float rr[8];
        const bool pf = (g < 31);
        if (pf) {
            const float* pn = pcb + (size_t)(g + 1) * 8 * 16384;
#pragma unroll
            for (int q = 0; q < 8; q++) rr[q] = pn[(size_t)q * 16384 + goff];
        }
#pragma unroll
        for (int q = 0; q < 8; q++) {
            const int c = g * 8 + q;
            const float* S = &buf[cur][q * 256];
            float top = S[j0]       * (1.f - wx) + S[j1]       * wx;
            float bot = S[128 + j0] * (1.f - wx) + S[128 + j1] * wx;
            float v = top * (1.f - wy) + bot * wy;
            v = fmaxf(v, 0.f);
            mx = fmaxf(mx, v);
            sm += v;
            dt = fmaf(sw[c], v, dt);
        }
        if (pf) {
#pragma unroll
            for (int q = 0; q < 8; q++) buf[cur ^ 1][q * 256 + t] = rr[q];
        }
        __syncthreads();
    }
    const int p = y * 256 + t;
    const size_t db = (size_t)b * 3 * HW;
    g_sagd[db + p]          = mx;
    g_sagd[db + HW + p]     = sm * (1.f / 256.f);
    g_sagd[db + 2 * HW + p] = dt + sb1d[0];
}

// ================= decoder channel stats v2: whole-channel smem + h-reuse =================
// grid (256, 4): c = blockIdx.x, b = blockIdx.y, 256 threads (thread = output column).
// Two phases stage source rows [0,65) then [63,128). Per 32-y chunk: 18 horizontal
// lerps (compile-time indices) reused by 32 vertical lerps. All index math folds.
__global__ void __launch_bounds__(256) k_dec_red(const float* __restrict__ xd) {
    __shared__ float S[65 * 128];        // 33.3 KB
    __shared__ float rsum[256], rmax[256];
    const int c = blockIdx.x, b = blockIdx.y, t = threadIdx.x;
    const float* pc = xd + ((size_t)b * 256 + c) * 16384;

    float px = (float)t * RATIO;
    int j0 = min((int)floorf(px), 127), j1 = min(j0 + 1, 127);
    float wx = px - (float)j0;

    float s = 0.f, m = 0.f;

#pragma unroll
    for (int ph = 0; ph < 2; ph++) {
        const int poff = ph ? 63 : 0;    // first staged source row
        if (ph) __syncthreads();         // protect S before reload
        {
            const float4* gsrc = (const float4*)(pc + poff * 128);
            float4* sdst = (float4*)S;
            for (int i = t; i < 65 * 32; i += 256) sdst[i] = gsrc[i];
        }
        __syncthreads();
#pragma unroll
        for (int k = 0; k < 4; k++) {
            const int y0 = ph * 128 + k * 32;
            const int rbase = (y0 * 127) / 255;
            float h[18];
#pragma unroll
            for (int r = 0; r < 18; r++) {
                const int row = min(rbase + r, 127) - poff;   // compile-time
                const float a = S[row * 128 + j0];
                h[r] = fmaf(wx, S[row * 128 + j1] - a, a);
            }
#pragma unroll
            for (int j = 0; j < 32; j++) {
                const int y  = y0 + j;
                const int i0 = (y * 127) / 255;               // exact floor
                const int i1 = min(i0 + 1, 127);
                const float wy = (float)y * RATIO - (float)i0;
                const float vlo = h[i0 - rbase], vhi = h[i1 - rbase];
                float v = fmaf(wy, vhi - vlo, vlo);
                v = fmaxf(v, 0.f);
                s += v;
                m = fmaxf(m, v);
            }
        }
    }
    __syncthreads();
    rsum[t] = s; rmax[t] = m;
    __syncthreads();
    for (int o = 128; o > 0; o >>= 1) {
        if (t < o) {
            rsum[t] += rsum[t + o];
            rmax[t] = fmaxf(rmax[t], rmax[t + o]);
        }
        __syncthreads();
    }
    if (t == 0) {
        g_decmean[b * 256 + c] = rsum[0] * (1.f / 65536.f);
        g_decmax [b * 256 + c] = rmax[0];
    }
}

// ================= channel MLP (parallel) =================
// grid (4): b = blockIdx.x, 256 threads: thread = (n 0..15, chunk 0..15)
__global__ void __launch_bounds__(256) k_mlp(
        const float* __restrict__ cwea, const float* __restrict__ cbea,
        const float* __restrict__ cwem, const float* __restrict__ cbem,
        const float* __restrict__ cwda, const float* __restrict__ cbda,
        const float* __restrict__ cwdm, const float* __restrict__ cbdm,
        const float* __restrict__ cwf,  const float* __restrict__ cbf) {
    __shared__ float part[256];
    __shared__ float tsm[16];
    const int b = blockIdx.x, t = threadIdx.x;
    const int n = t >> 4, ck = t & 15;
    float acc = 0.f;
#pragma unroll
    for (int i = 0; i < 8; i++) {
        int c = ck * 8 + i;
        acc += g_encsum[b * 128 + c] * (1.f / 65536.f) * cwea[n * 128 + c]
             + o2f(g_encmax[b * 128 + c]) * cwem[n * 128 + c];
    }
#pragma unroll
    for (int i = 0; i < 16; i++) {
        int c = ck * 16 + i;
        acc += g_decmean[b * 256 + c] * cwda[n * 256 + c]
             + g_decmax [b * 256 + c] * cwdm[n * 256 + c];
    }
    if (ck == 0) acc += cbea[n] + cbem[n] + cbda[n] + cbdm[n];
    part[t] = acc;
    __syncthreads();
    for (int o = 8; o > 0; o >>= 1) {
        if (ck < o) part[t] += part[t + o];
        __syncthreads();
    }
    if (ck == 0) tsm[n] = part[t];
    __syncthreads();
    if (t < 128) {
        float a = cbf[t];
#pragma unroll
        for (int q = 0; q < 16; q++) a = fmaf(tsm[q], cwf[t * 16 + q], a);
        g_ch[b * 128 + t] = 1.f / (1.f + __expf(-a));
    }
}

// ================= fused 7x7 conv (6 planes) + sigmoid =================
// grid (16, 16, 4): 16x16 output tile, 256 threads, 1 output/thread
__global__ void __launch_bounds__(256) k_conv(const float* __restrict__ sw2e,
                                              const float* __restrict__ sw2d,
                                              const float* __restrict__ sb2e,
                                              const float* __restrict__ sb2d) {
    __shared__ float pl[6][22 * 22];
    __shared__ float wsm[294];
    __shared__ float bv;
    const int tid = threadIdx.x;
    const int X0 = blockIdx.x * 16, Y0 = blockIdx.y * 16, b = blockIdx.z;
    for (int i = tid; i < 294; i += 256)
        wsm[i] = (i < 147) ? sw2e[i] : sw2d[i - 147];
    if (tid == 0) bv = sb2e[0] + sb2d[0];
    const size_t eb = (size_t)b * 3 * HW;
    for (int idx = tid; idx < 22 * 22; idx += 256) {
        int ry = idx / 22, rx = idx - ry * 22;
        int gy = Y0 + ry - 3, gx = X0 + rx - 3;
        float v0 = 0, v1 = 0, v2 = 0, v3 = 0, v4 = 0, v5 = 0;
        if (gy >= 0 && gy < 256 && gx >= 0 && gx < 256) {
            int p = gy * 256 + gx;
            v0 = g_sage[eb + p];
            v1 = g_sage[eb + HW + p];
            v2 = g_sage[eb + 2 * HW + p];
            v3 = g_sagd[eb + p];
            v4 = g_sagd[eb + HW + p];
            v5 = g_sagd[eb + 2 * HW + p];
        }
        pl[0][idx] = v0; pl[1][idx] = v1; pl[2][idx] = v2;
        pl[3][idx] = v3; pl[4][idx] = v4; pl[5][idx] = v5;
    }
    __syncthreads();
    const int tx = tid & 15, ty = tid >> 4;
    float acc = bv;
    for (int pp = 0; pp < 6; pp++)
#pragma unroll
        for (int ky = 0; ky < 7; ky++)
#pragma unroll
            for (int kx = 0; kx < 7; kx++)
                acc = fmaf(pl[pp][(ty + ky) * 22 + tx + kx], wsm[pp * 49 + ky * 7 + kx], acc);
    g_spat[(size_t)b * HW + (Y0 + ty) * 256 + X0 + tx] = 1.f / (1.f + __expf(-acc));
}

// ================= final multiply =================
// grid (64, 512): blockIdx.y = b*128+c, float4 per thread
__global__ void __launch_bounds__(256) k_final(const float* __restrict__ xe,
                                               float* __restrict__ out) {
    const int bc = blockIdx.y;
    const int b  = bc >> 7;
    const int i  = blockIdx.x * 256 + threadIdx.x;
    const float s = g_ch[bc];
    float4 xv = reinterpret_cast<const float4*>(xe)[(size_t)bc * 16384 + i];
    float4 sp = reinterpret_cast<const float4*>(g_spat)[(size_t)b * 16384 + i];
    float4 o;
    o.x = xv.x * sp.x * s;
    o.y = xv.y * sp.y * s;
    o.z = xv.z * sp.z * s;
    o.w = xv.w * sp.w * s;
    reinterpret_cast<float4*>(out)[(size_t)bc * 16384 + i] = o;
}

// ================= launch =================
extern "C" void kernel_launch(void* const* d_in, const int* in_sizes, int n_in,
                              void* d_out, int out_size) {
    const float* xe   = (const float*)d_in[0];
    const float* xd   = (const float*)d_in[1];
    const float* cwea = (const float*)d_in[2];
    const float* cbea = (const float*)d_in[3];
    const float* cwem = (const float*)d_in[4];
    const float* cbem = (const float*)d_in[5];
    const float* cwda = (const float*)d_in[6];
    const float* cbda = (const float*)d_in[7];
    const float* cwdm = (const float*)d_in[8];
    const float* cbdm = (const float*)d_in[9];
    const float* cwf  = (const float*)d_in[10];
    const float* cbf  = (const float*)d_in[11];
    const float* sw1e = (const float*)d_in[12];
    const float* sb1e = (const float*)d_in[13];
    const float* sw2e = (const float*)d_in[14];
    const float* sb2e = (const float*)d_in[15];
    const float* sw1d = (const float*)d_in[16];
    const float* sb1d = (const float*)d_in[17];
    const float* sw2d = (const float*)d_in[18];
    const float* sb2d = (const float*)d_in[19];
    float* out = (float*)d_out;

    k_init<<<1, 512>>>();
    k_enc<<<dim3(128, 4), 128>>>(xe, sw1e, sb1e);
    k_dec_pix<<<dim3(256, 4), 256>>>(xd, sw1d, sb1d);
    k_dec_red<<<dim3(256, 4), 256>>>(xd);
    k_mlp<<<4, 256>>>(cwea, cbea, cwem, cbem, cwda, cbda, cwdm, cbdm, cwf, cbf);
    k_conv<<<dim3(16, 16, 4), 256>>>(sw2e, sw2d, sb2e, sb2d);
    k_final<<<dim3(64, 512), 256>>>(xe, out);
}